// round 15
// baseline (speedup 1.0000x reference)
#include <cuda_runtime.h>
#include <cuda_fp16.h>
#include <cstdint>
#include <cstddef>

#define BROWS   8192
#define DIN     2048
#define DSTATE  2048
#define NSEG    4

#define BM 128
#define BN 32          // state-cols per block (x4 segments concurrently)
#define BK 64          // K halves per stage (4 k16 steps per barrier)
#define NK (DIN / BK)  // 32
#define SROW 72        // smem row stride in halves (64 data + 8 pad)
#define NSTAGE 3
#define NROWS 256                            // 128 x rows + 128 w rows
#define STG_HALVES (NROWS * SROW)            // 18432 halves
#define STG_BYTES  (STG_HALVES * 2)          // 36864 B per stage
#define SMEM_BYTES (NSTAGE * STG_BYTES)      // 110592 B

__device__ float g_gates[BROWS * NSEG];
__device__ __align__(16) __half g_xh[BROWS * DIN];           // 32 MB fp16 x
__device__ __align__(16) __half g_wh[NSEG * DSTATE * DIN];   // 32 MB fp16 W

// ---------------------------------------------------------------------------
// Helpers
// ---------------------------------------------------------------------------
#define MMA_F16(c, a, b0, b1)                                                   \
    asm volatile(                                                               \
        "mma.sync.aligned.m16n8k16.row.col.f32.f16.f16.f32 "                    \
        "{%0,%1,%2,%3}, {%4,%5,%6,%7}, {%8,%9}, {%0,%1,%2,%3};"                 \
        : "+f"(c[0]), "+f"(c[1]), "+f"(c[2]), "+f"(c[3])                        \
        : "r"(a[0]), "r"(a[1]), "r"(a[2]), "r"(a[3]), "r"(b0), "r"(b1))

#define LDSM_X4(r, addr)                                                        \
    asm volatile("ldmatrix.sync.aligned.m8n8.x4.shared.b16 {%0,%1,%2,%3}, [%4];"\
                 : "=r"((r)[0]), "=r"((r)[1]), "=r"((r)[2]), "=r"((r)[3])       \
                 : "r"(addr))

__device__ __forceinline__ void cp_async16(uint32_t saddr, const void* g) {
    asm volatile("cp.async.cg.shared.global [%0], [%1], 16;" ::"r"(saddr),
                 "l"(g) : "memory");
}
#define CP_COMMIT()  asm volatile("cp.async.commit_group;" ::: "memory")
#define CP_WAIT1()   asm volatile("cp.async.wait_group 1;" ::: "memory")

// ---------------------------------------------------------------------------
// Convert kernel: out[i] = half(in[i]) (rn). Vectorized float4 -> half4.
// ---------------------------------------------------------------------------
__global__ __launch_bounds__(256) void tohalf_kernel(const float* __restrict__ in,
                                                     __half* __restrict__ out,
                                                     int n4) {
    int i = blockIdx.x * blockDim.x + threadIdx.x;
    int stride = gridDim.x * blockDim.x;
    for (; i < n4; i += stride) {
        float4 v = ((const float4*)in)[i];
        __half2 h0 = __floats2half2_rn(v.x, v.y);
        __half2 h1 = __floats2half2_rn(v.z, v.w);
        uint2 pk;
        pk.x = *(uint32_t*)&h0;
        pk.y = *(uint32_t*)&h1;
        ((uint2*)out)[i] = pk;
    }
}

// ---------------------------------------------------------------------------
// Gate kernel: gates[b,s] = sigmoid(x[b,:] . W_gate[s,:] + b_gate[s])
// ---------------------------------------------------------------------------
__global__ __launch_bounds__(256) void gate_kernel(const float* __restrict__ x,
                                                   const float* __restrict__ Wg,
                                                   const float* __restrict__ bg) {
    int warp = threadIdx.x >> 5;
    int lane = threadIdx.x & 31;
    int b = blockIdx.x * 8 + warp;
    const float* xr = x + (size_t)b * DIN;

    float a0 = 0.f, a1 = 0.f, a2 = 0.f, a3 = 0.f;
    for (int i = lane * 4; i < DIN; i += 128) {
        float4 xv = *(const float4*)(xr + i);
        float4 w0 = *(const float4*)(Wg + 0 * DIN + i);
        float4 w1 = *(const float4*)(Wg + 1 * DIN + i);
        float4 w2 = *(const float4*)(Wg + 2 * DIN + i);
        float4 w3 = *(const float4*)(Wg + 3 * DIN + i);
        a0 += xv.x * w0.x + xv.y * w0.y + xv.z * w0.z + xv.w * w0.w;
        a1 += xv.x * w1.x + xv.y * w1.y + xv.z * w1.z + xv.w * w1.w;
        a2 += xv.x * w2.x + xv.y * w2.y + xv.z * w2.z + xv.w * w2.w;
        a3 += xv.x * w3.x + xv.y * w3.y + xv.z * w3.z + xv.w * w3.w;
    }
#pragma unroll
    for (int off = 16; off; off >>= 1) {
        a0 += __shfl_xor_sync(0xFFFFFFFFu, a0, off);
        a1 += __shfl_xor_sync(0xFFFFFFFFu, a1, off);
        a2 += __shfl_xor_sync(0xFFFFFFFFu, a2, off);
        a3 += __shfl_xor_sync(0xFFFFFFFFu, a3, off);
    }
    if (lane == 0) {
        g_gates[b * 4 + 0] = 1.f / (1.f + __expf(-(a0 + bg[0])));
        g_gates[b * 4 + 1] = 1.f / (1.f + __expf(-(a1 + bg[1])));
        g_gates[b * 4 + 2] = 1.f / (1.f + __expf(-(a2 + bg[2])));
        g_gates[b * 4 + 3] = 1.f / (1.f + __expf(-(a3 + bg[3])));
    }
}

// ---------------------------------------------------------------------------
// Fused segment-GEMM + epilogue kernel (fp16 mma m16n8k16, fp32 accumulate).
// 128 (batch rows) x 32 (state cols) x 4 segments per CTA, 256 threads =
// 8 warps as 4 (m) x 2 (n); warp tile 32 x 16 per segment.
// BK=64 K-depth per barrier (4 k16 steps) -> 32 barriers. 3-stage cp.async
// ring (prefetch distance 2, wait_group 1), 110.6 KB smem -> 2 CTAs/SM.
// Halves L2 traffic vs the BM=64 variant (W amortized over 2x m-rows).
// ---------------------------------------------------------------------------
__global__ __launch_bounds__(256, 2) void dendritic_kernel(
    const float* __restrict__ b_seg,  // (4, 2048)
    const float* __restrict__ th,     // (4, 2048)
    float* __restrict__ out)          // (8192, 2048)
{
    extern __shared__ __half smh[];

    const int tid = threadIdx.x;
    const int bm = blockIdx.x;  // batch tile (fast dim -> W slice stays hot in L2)
    const int bn = blockIdx.y;  // state tile

    const int warpId = tid >> 5;
    const int lane = tid & 31;
    const int wm = warpId & 3;   // m offset = wm*32
    const int wn = warpId >> 2;  // n offset = wn*16
    const int g = lane >> 2;     // row within 8
    const int qb = lane & 3;     // k quad

    const uint32_t sm_base = (uint32_t)__cvta_generic_to_shared(smh);

    // ---- ldmatrix lane addressing (byte offsets) ----
    const int grp = lane >> 3;
    const int rowoff = lane & 7;
    // A matrices {0..3} = {rows+0-7 k0-7, rows+8-15 k0-7, rows+0-7 k8-15, rows+8-15 k8-15}
    uint32_t aOff[2];
#pragma unroll
    for (int mi = 0; mi < 2; mi++) {
        int row = wm * 32 + mi * 16 + (grp & 1) * 8 + rowoff;
        int kof = (grp >> 1) * 8;  // halves
        aOff[mi] = (uint32_t)(row * SROW + kof) * 2;
    }
    // B matrices {0..3} = {ni0 k0-7, ni0 k8-15, ni1 k0-7, ni1 k8-15}
    uint32_t bOff[NSEG];
#pragma unroll
    for (int s = 0; s < NSEG; s++) {
        int row = 128 + s * BN + wn * 16 + (grp >> 1) * 8 + rowoff;
        int kof = (grp & 1) * 8;  // halves
        bOff[s] = (uint32_t)(row * SROW + kof) * 2;
    }

    // ---- fill assignments: 2048 16B chunks per stage, 8 per thread ----
    // r0 = tid>>3 (0..31), col_h = (tid&7)*8 halves (16B chunk).
    // x: rows r0+32j, j=0..3.  w: smem row 128 + r0 + 32*jw, jw=0..3;
    //    seg = jw, d = bn*32 + r0.
    const int r0 = tid >> 3;
    const int col_h = (tid & 7) * 8;
    const __half* gx0 = g_xh + (size_t)(bm * BM + r0) * DIN + col_h;
    const __half* gw0 = g_wh + ((size_t)bn * BN + r0) * DIN + col_h;
    const uint32_t sa_x = sm_base + (uint32_t)(r0 * SROW + col_h) * 2;
    const uint32_t sa_w = sm_base + (uint32_t)((128 + r0) * SROW + col_h) * 2;

    float acc[NSEG][2][2][4];
#pragma unroll
    for (int s = 0; s < NSEG; s++)
#pragma unroll
        for (int mi = 0; mi < 2; mi++)
#pragma unroll
            for (int ni = 0; ni < 2; ni++)
#pragma unroll
                for (int e = 0; e < 4; e++) acc[s][mi][ni][e] = 0.f;

    // ---- prologue: issue stages 0,1 ----
#pragma unroll
    for (int p = 0; p < 2; p++) {
        const uint32_t sb = (uint32_t)(p * STG_BYTES);
        const int ko = p * BK;
#pragma unroll
        for (int j = 0; j < 4; j++)
            cp_async16(sa_x + sb + (uint32_t)(32 * j * SROW) * 2,
                       gx0 + (size_t)(32 * j) * DIN + ko);
#pragma unroll
        for (int jw = 0; jw < 4; jw++)
            cp_async16(sa_w + sb + (uint32_t)(32 * jw * SROW) * 2,
                       gw0 + (size_t)jw * DSTATE * DIN + ko);
        CP_COMMIT();
    }

    int st = 0;
    for (int kt = 0; kt < NK; kt++) {
        CP_WAIT1();
        __syncthreads();  // stage kt visible; compute of stage (kt-1) done

        if (kt + 2 < NK) {
            const int ns = (st + 2 >= NSTAGE) ? st + 2 - NSTAGE : st + 2;
            const uint32_t sb = (uint32_t)(ns * STG_BYTES);
            const int ko = (kt + 2) * BK;
#pragma unroll
            for (int j = 0; j < 4; j++)
                cp_async16(sa_x + sb + (uint32_t)(32 * j * SROW) * 2,
                           gx0 + (size_t)(32 * j) * DIN + ko);
#pragma unroll
            for (int jw = 0; jw < 4; jw++)
                cp_async16(sa_w + sb + (uint32_t)(32 * jw * SROW) * 2,
                           gw0 + (size_t)jw * DSTATE * DIN + ko);
        }
        CP_COMMIT();  // uniform one group per kt (may be empty near the tail)

        const uint32_t stage = sm_base + (uint32_t)(st * STG_BYTES);
#pragma unroll
        for (int k16 = 0; k16 < 4; k16++) {
            const uint32_t kb = (uint32_t)(k16 * 16 * 2);  // 16 halves per step

            uint32_t A[2][4];
#pragma unroll
            for (int mi = 0; mi < 2; mi++)
                LDSM_X4(A[mi], stage + aOff[mi] + kb);

            uint32_t B[NSEG][4];  // {b0_ni0, b1_ni0, b0_ni1, b1_ni1}
#pragma unroll
            for (int s = 0; s < NSEG; s++)
                LDSM_X4(B[s], stage + bOff[s] + kb);

#pragma unroll
            for (int s = 0; s < NSEG; s++) {
#pragma unroll
                for (int ni = 0; ni < 2; ni++) {
#pragma unroll
                    for (int mi = 0; mi < 2; mi++) {
                        MMA_F16(acc[s][mi][ni], A[mi], B[s][ni * 2],
                                B[s][ni * 2 + 1]);
                    }
                }
            }
        }

        st = (st + 1 >= NSTAGE) ? 0 : st + 1;
    }

    // ---- epilogue: bias, plateau, gate, sum + 0.1 * signed geo-mean ----
    const int bbase = bm * BM;
    const int dbase = bn * BN;

#pragma unroll
    for (int mi = 0; mi < 2; mi++) {
#pragma unroll
        for (int hh = 0; hh < 2; hh++) {
            const int rloc = wm * 32 + mi * 16 + g + hh * 8;
            const int brow = bbase + rloc;
            float4 gv = *(const float4*)(&g_gates[brow * 4]);
            float gt[NSEG] = {gv.x, gv.y, gv.z, gv.w};
#pragma unroll
            for (int ni = 0; ni < 2; ni++) {
#pragma unroll
                for (int e = 0; e < 2; e++) {
                    const int d = dbase + wn * 16 + ni * 8 + qb * 2 + e;
                    float sumv = 0.f, prodv = 1.f;
#pragma unroll
                    for (int s = 0; s < NSEG; s++) {
                        float seg = acc[s][mi][ni][hh * 2 + e] + b_seg[s * DSTATE + d];
                        float z = 5.f * (seg - th[s * DSTATE + d]);
                        float p = 1.f / (1.f + __expf(-z));
                        float vv = seg * p * gt[s];
                        sumv += vv;
                        prodv *= vv;
                    }
                    float r4 = sqrtf(sqrtf(fabsf(prodv)));
                    out[(size_t)brow * DSTATE + d] = sumv + 0.1f * copysignf(r4, prodv);
                }
            }
        }
    }
}

// ---------------------------------------------------------------------------
extern "C" void kernel_launch(void* const* d_in, const int* in_sizes, int n_in,
                              void* d_out, int out_size) {
    const float* x      = (const float*)d_in[0];
    const float* W_seg  = (const float*)d_in[1];
    const float* b_seg  = (const float*)d_in[2];
    const float* thresh = (const float*)d_in[3];
    const float* W_gate = (const float*)d_in[4];
    const float* b_gate = (const float*)d_in[5];
    float* out = (float*)d_out;
    (void)in_sizes; (void)n_in; (void)out_size;

    __half* gx;
    __half* gw;
    cudaGetSymbolAddress((void**)&gx, g_xh);
    cudaGetSymbolAddress((void**)&gw, g_wh);

    cudaFuncSetAttribute(dendritic_kernel,
                         cudaFuncAttributeMaxDynamicSharedMemorySize, SMEM_BYTES);

    tohalf_kernel<<<1184, 256>>>(x, gx, BROWS * DIN / 4);
    tohalf_kernel<<<1184, 256>>>(W_seg, gw, NSEG * DSTATE * DIN / 4);
    gate_kernel<<<BROWS / 8, 256>>>(x, W_gate, b_gate);

    dim3 grid(BROWS / BM, DSTATE / BN);  // (64, 64), bm fast
    dendritic_kernel<<<grid, 256, SMEM_BYTES>>>(b_seg, thresh, out);
}

// round 16
// speedup vs baseline: 1.3055x; 1.3055x over previous
#include <cuda_runtime.h>
#include <cuda_fp16.h>
#include <cstdint>
#include <cstddef>

#define BROWS   8192
#define DIN     2048
#define DSTATE  2048
#define NSEG    4

#define BM 64
#define BN 32          // state-cols per block (x4 segments concurrently)
#define BK 64          // K halves per stage (4 k16 steps per barrier)
#define NK (DIN / BK)  // 32
#define SROW 72        // smem row stride in halves (64 data + 8 pad)
#define NSTAGE 2
#define NROWS 192                            // 64 x rows + 128 w rows
#define STG_HALVES (NROWS * SROW)            // 13824 halves
#define STG_BYTES  (STG_HALVES * 2)          // 27648 B per stage
#define SMEM_BYTES (NSTAGE * STG_BYTES)      // 55296 B

__device__ float g_gates[BROWS * NSEG];
__device__ __align__(16) __half g_xh[BROWS * DIN];           // 32 MB fp16 x
__device__ __align__(16) __half g_wh[NSEG * DSTATE * DIN];   // 32 MB fp16 W

// ---------------------------------------------------------------------------
// Helpers
// ---------------------------------------------------------------------------
#define MMA_F16(c, a, b0, b1)                                                   \
    asm volatile(                                                               \
        "mma.sync.aligned.m16n8k16.row.col.f32.f16.f16.f32 "                    \
        "{%0,%1,%2,%3}, {%4,%5,%6,%7}, {%8,%9}, {%0,%1,%2,%3};"                 \
        : "+f"(c[0]), "+f"(c[1]), "+f"(c[2]), "+f"(c[3])                        \
        : "r"(a[0]), "r"(a[1]), "r"(a[2]), "r"(a[3]), "r"(b0), "r"(b1))

#define LDSM_X4(r, addr)                                                        \
    asm volatile("ldmatrix.sync.aligned.m8n8.x4.shared.b16 {%0,%1,%2,%3}, [%4];"\
                 : "=r"((r)[0]), "=r"((r)[1]), "=r"((r)[2]), "=r"((r)[3])       \
                 : "r"(addr))

__device__ __forceinline__ void cp_async16(uint32_t saddr, const void* g) {
    asm volatile("cp.async.cg.shared.global [%0], [%1], 16;" ::"r"(saddr),
                 "l"(g) : "memory");
}
#define CP_COMMIT()  asm volatile("cp.async.commit_group;" ::: "memory")
#define CP_WAIT0()   asm volatile("cp.async.wait_group 0;" ::: "memory")

// ---------------------------------------------------------------------------
// Convert kernel: out[i] = half(in[i]) (rn). Vectorized float4 -> half4.
// ---------------------------------------------------------------------------
__global__ __launch_bounds__(256) void tohalf_kernel(const float* __restrict__ in,
                                                     __half* __restrict__ out,
                                                     int n4) {
    int i = blockIdx.x * blockDim.x + threadIdx.x;
    int stride = gridDim.x * blockDim.x;
    for (; i < n4; i += stride) {
        float4 v = ((const float4*)in)[i];
        __half2 h0 = __floats2half2_rn(v.x, v.y);
        __half2 h1 = __floats2half2_rn(v.z, v.w);
        uint2 pk;
        pk.x = *(uint32_t*)&h0;
        pk.y = *(uint32_t*)&h1;
        ((uint2*)out)[i] = pk;
    }
}

// ---------------------------------------------------------------------------
// Gate kernel: gates[b,s] = sigmoid(x[b,:] . W_gate[s,:] + b_gate[s])
// ---------------------------------------------------------------------------
__global__ __launch_bounds__(256) void gate_kernel(const float* __restrict__ x,
                                                   const float* __restrict__ Wg,
                                                   const float* __restrict__ bg) {
    int warp = threadIdx.x >> 5;
    int lane = threadIdx.x & 31;
    int b = blockIdx.x * 8 + warp;
    const float* xr = x + (size_t)b * DIN;

    float a0 = 0.f, a1 = 0.f, a2 = 0.f, a3 = 0.f;
    for (int i = lane * 4; i < DIN; i += 128) {
        float4 xv = *(const float4*)(xr + i);
        float4 w0 = *(const float4*)(Wg + 0 * DIN + i);
        float4 w1 = *(const float4*)(Wg + 1 * DIN + i);
        float4 w2 = *(const float4*)(Wg + 2 * DIN + i);
        float4 w3 = *(const float4*)(Wg + 3 * DIN + i);
        a0 += xv.x * w0.x + xv.y * w0.y + xv.z * w0.z + xv.w * w0.w;
        a1 += xv.x * w1.x + xv.y * w1.y + xv.z * w1.z + xv.w * w1.w;
        a2 += xv.x * w2.x + xv.y * w2.y + xv.z * w2.z + xv.w * w2.w;
        a3 += xv.x * w3.x + xv.y * w3.y + xv.z * w3.z + xv.w * w3.w;
    }
#pragma unroll
    for (int off = 16; off; off >>= 1) {
        a0 += __shfl_xor_sync(0xFFFFFFFFu, a0, off);
        a1 += __shfl_xor_sync(0xFFFFFFFFu, a1, off);
        a2 += __shfl_xor_sync(0xFFFFFFFFu, a2, off);
        a3 += __shfl_xor_sync(0xFFFFFFFFu, a3, off);
    }
    if (lane == 0) {
        g_gates[b * 4 + 0] = 1.f / (1.f + __expf(-(a0 + bg[0])));
        g_gates[b * 4 + 1] = 1.f / (1.f + __expf(-(a1 + bg[1])));
        g_gates[b * 4 + 2] = 1.f / (1.f + __expf(-(a2 + bg[2])));
        g_gates[b * 4 + 3] = 1.f / (1.f + __expf(-(a3 + bg[3])));
    }
}

// ---------------------------------------------------------------------------
// Fused segment-GEMM + epilogue kernel (fp16 mma m16n8k16, fp32 accumulate).
// R14 skeleton: 64 x 32 x 4seg per CTA, 128 threads (2m x 2n warps),
// BK=64, 2-stage ring, 4 CTAs/SM. Delta vs R14: cp.async producer issue is
// interleaved INTO the k16 compute blocks (x loads in k16=0, W loads in
// k16=1/2, commit after k16=2) so the ~96-cyc LDGSTS burst runs under the
// tensor pipe instead of serially in front of it.
// ---------------------------------------------------------------------------
__global__ __launch_bounds__(128, 4) void dendritic_kernel(
    const float* __restrict__ b_seg,  // (4, 2048)
    const float* __restrict__ th,     // (4, 2048)
    float* __restrict__ out)          // (8192, 2048)
{
    extern __shared__ __half smh[];

    const int tid = threadIdx.x;
    const int bm = blockIdx.x;  // batch tile (fast dim -> W slice stays hot in L2)
    const int bn = blockIdx.y;  // state tile

    const int warpId = tid >> 5;
    const int lane = tid & 31;
    const int wm = warpId & 1;   // m offset = wm*32
    const int wn = warpId >> 1;  // n offset = wn*16
    const int g = lane >> 2;     // row within 8
    const int qb = lane & 3;     // k quad

    const uint32_t sm_base = (uint32_t)__cvta_generic_to_shared(smh);

    // ---- ldmatrix lane addressing (byte offsets) ----
    const int grp = lane >> 3;
    const int rowoff = lane & 7;
    uint32_t aOff[2];
#pragma unroll
    for (int mi = 0; mi < 2; mi++) {
        int row = wm * 32 + mi * 16 + (grp & 1) * 8 + rowoff;
        int kof = (grp >> 1) * 8;  // halves
        aOff[mi] = (uint32_t)(row * SROW + kof) * 2;
    }
    uint32_t bOff[NSEG];
#pragma unroll
    for (int s = 0; s < NSEG; s++) {
        int row = 64 + s * BN + wn * 16 + (grp >> 1) * 8 + rowoff;
        int kof = (grp & 1) * 8;  // halves
        bOff[s] = (uint32_t)(row * SROW + kof) * 2;
    }

    // ---- fill assignments: 1536 16B chunks per stage, 12 per thread ----
    const int r0 = tid >> 3;
    const int col_h = (tid & 7) * 8;
    const __half* gx0 = g_xh + (size_t)(bm * BM + r0) * DIN + col_h;
    const __half* gw0 = g_wh + ((size_t)bn * BN + r0) * DIN + col_h;
    const uint32_t sa_x = sm_base + (uint32_t)(r0 * SROW + col_h) * 2;
    const uint32_t sa_w = sm_base + (uint32_t)((64 + r0) * SROW + col_h) * 2;

    float acc[NSEG][2][2][4];
#pragma unroll
    for (int s = 0; s < NSEG; s++)
#pragma unroll
        for (int mi = 0; mi < 2; mi++)
#pragma unroll
            for (int ni = 0; ni < 2; ni++)
#pragma unroll
                for (int e = 0; e < 4; e++) acc[s][mi][ni][e] = 0.f;

    // ---- prologue: issue stage 0 ----
#pragma unroll
    for (int j = 0; j < 4; j++)
        cp_async16(sa_x + (uint32_t)(16 * j * SROW) * 2,
                   gx0 + (size_t)(16 * j) * DIN);
#pragma unroll
    for (int jw = 0; jw < 8; jw++) {
        const size_t goff = ((size_t)(jw >> 1) * DSTATE + 16 * (jw & 1)) * DIN;
        cp_async16(sa_w + (uint32_t)(16 * jw * SROW) * 2, gw0 + goff);
    }
    CP_COMMIT();

    int st = 0;
    for (int kt = 0; kt < NK; kt++) {
        CP_WAIT0();
        __syncthreads();  // stage kt visible; prior compute on other stage done

        const bool pf = (kt + 1 < NK);
        const uint32_t sb = (uint32_t)((st ^ 1) * STG_BYTES);
        const int ko = (kt + 1) * BK;
        const uint32_t stage = sm_base + (uint32_t)(st * STG_BYTES);

#pragma unroll
        for (int k16 = 0; k16 < 4; k16++) {
            const uint32_t kb = (uint32_t)(k16 * 16 * 2);  // 16 halves per step

            uint32_t A[2][4];
#pragma unroll
            for (int mi = 0; mi < 2; mi++)
                LDSM_X4(A[mi], stage + aOff[mi] + kb);

            uint32_t B[NSEG][4];  // {b0_ni0, b1_ni0, b0_ni1, b1_ni1}
#pragma unroll
            for (int s = 0; s < NSEG; s++)
                LDSM_X4(B[s], stage + bOff[s] + kb);

            // ---- producer issue interleaved under the tensor shadow ----
            if (k16 == 0 && pf) {
#pragma unroll
                for (int j = 0; j < 4; j++)
                    cp_async16(sa_x + sb + (uint32_t)(16 * j * SROW) * 2,
                               gx0 + (size_t)(16 * j) * DIN + ko);
            } else if (k16 == 1 && pf) {
#pragma unroll
                for (int jw = 0; jw < 4; jw++) {
                    const size_t goff =
                        ((size_t)(jw >> 1) * DSTATE + 16 * (jw & 1)) * DIN;
                    cp_async16(sa_w + sb + (uint32_t)(16 * jw * SROW) * 2,
                               gw0 + goff + ko);
                }
            } else if (k16 == 2) {
                if (pf) {
#pragma unroll
                    for (int jw = 4; jw < 8; jw++) {
                        const size_t goff =
                            ((size_t)(jw >> 1) * DSTATE + 16 * (jw & 1)) * DIN;
                        cp_async16(sa_w + sb + (uint32_t)(16 * jw * SROW) * 2,
                                   gw0 + goff + ko);
                    }
                }
                CP_COMMIT();  // uniform one group per kt (may be empty at tail)
            }

#pragma unroll
            for (int s = 0; s < NSEG; s++) {
#pragma unroll
                for (int ni = 0; ni < 2; ni++) {
#pragma unroll
                    for (int mi = 0; mi < 2; mi++) {
                        MMA_F16(acc[s][mi][ni], A[mi], B[s][ni * 2],
                                B[s][ni * 2 + 1]);
                    }
                }
            }
        }

        st ^= 1;
    }

    // ---- epilogue: bias, plateau, gate, sum + 0.1 * signed geo-mean ----
    const int bbase = bm * BM;
    const int dbase = bn * BN;

#pragma unroll
    for (int mi = 0; mi < 2; mi++) {
#pragma unroll
        for (int hh = 0; hh < 2; hh++) {
            const int rloc = wm * 32 + mi * 16 + g + hh * 8;
            const int brow = bbase + rloc;
            float4 gv = *(const float4*)(&g_gates[brow * 4]);
            float gt[NSEG] = {gv.x, gv.y, gv.z, gv.w};
#pragma unroll
            for (int ni = 0; ni < 2; ni++) {
#pragma unroll
                for (int e = 0; e < 2; e++) {
                    const int d = dbase + wn * 16 + ni * 8 + qb * 2 + e;
                    float sumv = 0.f, prodv = 1.f;
#pragma unroll
                    for (int s = 0; s < NSEG; s++) {
                        float seg = acc[s][mi][ni][hh * 2 + e] + b_seg[s * DSTATE + d];
                        float z = 5.f * (seg - th[s * DSTATE + d]);
                        float p = 1.f / (1.f + __expf(-z));
                        float vv = seg * p * gt[s];
                        sumv += vv;
                        prodv *= vv;
                    }
                    float r4 = sqrtf(sqrtf(fabsf(prodv)));
                    out[(size_t)brow * DSTATE + d] = sumv + 0.1f * copysignf(r4, prodv);
                }
            }
        }
    }
}

// ---------------------------------------------------------------------------
extern "C" void kernel_launch(void* const* d_in, const int* in_sizes, int n_in,
                              void* d_out, int out_size) {
    const float* x      = (const float*)d_in[0];
    const float* W_seg  = (const float*)d_in[1];
    const float* b_seg  = (const float*)d_in[2];
    const float* thresh = (const float*)d_in[3];
    const float* W_gate = (const float*)d_in[4];
    const float* b_gate = (const float*)d_in[5];
    float* out = (float*)d_out;
    (void)in_sizes; (void)n_in; (void)out_size;

    __half* gx;
    __half* gw;
    cudaGetSymbolAddress((void**)&gx, g_xh);
    cudaGetSymbolAddress((void**)&gw, g_wh);

    cudaFuncSetAttribute(dendritic_kernel,
                         cudaFuncAttributeMaxDynamicSharedMemorySize, SMEM_BYTES);

    tohalf_kernel<<<1184, 256>>>(x, gx, BROWS * DIN / 4);
    tohalf_kernel<<<1184, 256>>>(W_seg, gw, NSEG * DSTATE * DIN / 4);
    gate_kernel<<<BROWS / 8, 256>>>(x, W_gate, b_gate);

    dim3 grid(BROWS / BM, DSTATE / BN);  // (128, 64), bm fast
    dendritic_kernel<<<grid, 128, SMEM_BYTES>>>(b_seg, thresh, out);
}

// round 17
// speedup vs baseline: 1.3194x; 1.0107x over previous
#include <cuda_runtime.h>
#include <cuda_fp16.h>
#include <cstdint>
#include <cstddef>

#define BROWS   8192
#define DIN     2048
#define DSTATE  2048
#define NSEG    4

#define BM 64
#define BN 32          // state-cols per block (x4 segments concurrently)
#define BK 64          // K halves per stage (4 k16 steps per barrier)
#define NK (DIN / BK)  // 32
#define SROW 72        // smem row stride in halves (64 data + 8 pad)
#define NSTAGE 2
#define NROWS 192                            // 64 x rows + 128 w rows
#define STG_HALVES (NROWS * SROW)            // 13824 halves
#define STG_BYTES  (STG_HALVES * 2)          // 27648 B per stage
#define SMEM_BYTES (NSTAGE * STG_BYTES)      // 55296 B

__device__ float g_gates[BROWS * NSEG];
__device__ __align__(16) __half g_xh[BROWS * DIN];           // 32 MB fp16 x
__device__ __align__(16) __half g_wh[NSEG * DSTATE * DIN];   // 32 MB fp16 W

// ---------------------------------------------------------------------------
// Helpers
// ---------------------------------------------------------------------------
#define MMA_F16(c, a, b0, b1)                                                   \
    asm volatile(                                                               \
        "mma.sync.aligned.m16n8k16.row.col.f32.f16.f16.f32 "                    \
        "{%0,%1,%2,%3}, {%4,%5,%6,%7}, {%8,%9}, {%0,%1,%2,%3};"                 \
        : "+f"(c[0]), "+f"(c[1]), "+f"(c[2]), "+f"(c[3])                        \
        : "r"(a[0]), "r"(a[1]), "r"(a[2]), "r"(a[3]), "r"(b0), "r"(b1))

#define LDSM_X4(r, addr)                                                        \
    asm volatile("ldmatrix.sync.aligned.m8n8.x4.shared.b16 {%0,%1,%2,%3}, [%4];"\
                 : "=r"((r)[0]), "=r"((r)[1]), "=r"((r)[2]), "=r"((r)[3])       \
                 : "r"(addr))

__device__ __forceinline__ void cp_async16(uint32_t saddr, const void* g) {
    asm volatile("cp.async.cg.shared.global [%0], [%1], 16;" ::"r"(saddr),
                 "l"(g) : "memory");
}
#define CP_COMMIT()  asm volatile("cp.async.commit_group;" ::: "memory")
#define CP_WAIT0()   asm volatile("cp.async.wait_group 0;" ::: "memory")

// ---------------------------------------------------------------------------
// Convert kernel: out[i] = half(in[i]) (rn). Vectorized float4 -> half4.
// ---------------------------------------------------------------------------
__global__ __launch_bounds__(256) void tohalf_kernel(const float* __restrict__ in,
                                                     __half* __restrict__ out,
                                                     int n4) {
    int i = blockIdx.x * blockDim.x + threadIdx.x;
    int stride = gridDim.x * blockDim.x;
    for (; i < n4; i += stride) {
        float4 v = ((const float4*)in)[i];
        __half2 h0 = __floats2half2_rn(v.x, v.y);
        __half2 h1 = __floats2half2_rn(v.z, v.w);
        uint2 pk;
        pk.x = *(uint32_t*)&h0;
        pk.y = *(uint32_t*)&h1;
        ((uint2*)out)[i] = pk;
    }
}

// ---------------------------------------------------------------------------
// Gate kernel: gates[b,s] = sigmoid(x[b,:] . W_gate[s,:] + b_gate[s])
// ---------------------------------------------------------------------------
__global__ __launch_bounds__(256) void gate_kernel(const float* __restrict__ x,
                                                   const float* __restrict__ Wg,
                                                   const float* __restrict__ bg) {
    int warp = threadIdx.x >> 5;
    int lane = threadIdx.x & 31;
    int b = blockIdx.x * 8 + warp;
    const float* xr = x + (size_t)b * DIN;

    float a0 = 0.f, a1 = 0.f, a2 = 0.f, a3 = 0.f;
    for (int i = lane * 4; i < DIN; i += 128) {
        float4 xv = *(const float4*)(xr + i);
        float4 w0 = *(const float4*)(Wg + 0 * DIN + i);
        float4 w1 = *(const float4*)(Wg + 1 * DIN + i);
        float4 w2 = *(const float4*)(Wg + 2 * DIN + i);
        float4 w3 = *(const float4*)(Wg + 3 * DIN + i);
        a0 += xv.x * w0.x + xv.y * w0.y + xv.z * w0.z + xv.w * w0.w;
        a1 += xv.x * w1.x + xv.y * w1.y + xv.z * w1.z + xv.w * w1.w;
        a2 += xv.x * w2.x + xv.y * w2.y + xv.z * w2.z + xv.w * w2.w;
        a3 += xv.x * w3.x + xv.y * w3.y + xv.z * w3.z + xv.w * w3.w;
    }
#pragma unroll
    for (int off = 16; off; off >>= 1) {
        a0 += __shfl_xor_sync(0xFFFFFFFFu, a0, off);
        a1 += __shfl_xor_sync(0xFFFFFFFFu, a1, off);
        a2 += __shfl_xor_sync(0xFFFFFFFFu, a2, off);
        a3 += __shfl_xor_sync(0xFFFFFFFFu, a3, off);
    }
    if (lane == 0) {
        g_gates[b * 4 + 0] = 1.f / (1.f + __expf(-(a0 + bg[0])));
        g_gates[b * 4 + 1] = 1.f / (1.f + __expf(-(a1 + bg[1])));
        g_gates[b * 4 + 2] = 1.f / (1.f + __expf(-(a2 + bg[2])));
        g_gates[b * 4 + 3] = 1.f / (1.f + __expf(-(a3 + bg[3])));
    }
}

// ---------------------------------------------------------------------------
// Fused segment-GEMM + epilogue kernel (fp16 mma m16n8k16, fp32 accumulate).
// R16 skeleton: 64 x 32 x 4seg per CTA, 128 threads (2m x 2n warps),
// BK=64, 2-stage ring, 4 CTAs/SM, producer issue interleaved into compute.
// Delta vs R16: k16=3's fragments for segs 2,3 (plus A) are HELD across the
// stage barrier and their 8 MMAs issue immediately after __syncthreads,
// covering barrier release + the k0 LDSM ramp with guaranteed tensor work.
// Per-accumulator MMA order unchanged -> numerics bit-identical.
// ---------------------------------------------------------------------------
__global__ __launch_bounds__(128, 4) void dendritic_kernel(
    const float* __restrict__ b_seg,  // (4, 2048)
    const float* __restrict__ th,     // (4, 2048)
    float* __restrict__ out)          // (8192, 2048)
{
    extern __shared__ __half smh[];

    const int tid = threadIdx.x;
    const int bm = blockIdx.x;  // batch tile (fast dim -> W slice stays hot in L2)
    const int bn = blockIdx.y;  // state tile

    const int warpId = tid >> 5;
    const int lane = tid & 31;
    const int wm = warpId & 1;   // m offset = wm*32
    const int wn = warpId >> 1;  // n offset = wn*16
    const int g = lane >> 2;     // row within 8
    const int qb = lane & 3;     // k quad

    const uint32_t sm_base = (uint32_t)__cvta_generic_to_shared(smh);

    // ---- ldmatrix lane addressing (byte offsets; mi/s strides are consts) ----
    const int grp = lane >> 3;
    const int rowoff = lane & 7;
    uint32_t aOff0;
    {
        int row = wm * 32 + (grp & 1) * 8 + rowoff;
        int kof = (grp >> 1) * 8;  // halves
        aOff0 = (uint32_t)(row * SROW + kof) * 2;
    }
    uint32_t bOff0;
    {
        int row = 64 + wn * 16 + (grp >> 1) * 8 + rowoff;
        int kof = (grp & 1) * 8;  // halves
        bOff0 = (uint32_t)(row * SROW + kof) * 2;
    }
#define A_OFF(mi)  (aOff0 + (uint32_t)((mi) * 16 * SROW * 2))
#define B_OFF(s)   (bOff0 + (uint32_t)((s) * BN * SROW * 2))

    // ---- fill assignments: 1536 16B chunks per stage, 12 per thread ----
    const int r0 = tid >> 3;
    const int col_h = (tid & 7) * 8;
    const __half* gx0 = g_xh + (size_t)(bm * BM + r0) * DIN + col_h;
    const __half* gw0 = g_wh + ((size_t)bn * BN + r0) * DIN + col_h;
    const uint32_t sa_x = sm_base + (uint32_t)(r0 * SROW + col_h) * 2;
    const uint32_t sa_w = sm_base + (uint32_t)((64 + r0) * SROW + col_h) * 2;

    float acc[NSEG][2][2][4];
#pragma unroll
    for (int s = 0; s < NSEG; s++)
#pragma unroll
        for (int mi = 0; mi < 2; mi++)
#pragma unroll
            for (int ni = 0; ni < 2; ni++)
#pragma unroll
                for (int e = 0; e < 4; e++) acc[s][mi][ni][e] = 0.f;

    // ---- prologue: issue stage 0 ----
#pragma unroll
    for (int j = 0; j < 4; j++)
        cp_async16(sa_x + (uint32_t)(16 * j * SROW) * 2,
                   gx0 + (size_t)(16 * j) * DIN);
#pragma unroll
    for (int jw = 0; jw < 8; jw++) {
        const size_t goff = ((size_t)(jw >> 1) * DSTATE + 16 * (jw & 1)) * DIN;
        cp_async16(sa_w + (uint32_t)(16 * jw * SROW) * 2, gw0 + goff);
    }
    CP_COMMIT();

    // held fragments of k16=3 (A for both mi; B for segs 2,3)
    uint32_t Ah[2][4];
    uint32_t Bh[2][4];

    int st = 0;
    for (int kt = 0; kt < NK; kt++) {
        CP_WAIT0();
        __syncthreads();  // stage kt visible; prior compute on other stage done

        // ---- deferred MMAs of (kt-1, k16=3), segs 2,3 — cover the barrier ----
        if (kt > 0) {
#pragma unroll
            for (int sh = 0; sh < 2; sh++) {
#pragma unroll
                for (int ni = 0; ni < 2; ni++) {
#pragma unroll
                    for (int mi = 0; mi < 2; mi++) {
                        MMA_F16(acc[2 + sh][mi][ni], Ah[mi], Bh[sh][ni * 2],
                                Bh[sh][ni * 2 + 1]);
                    }
                }
            }
        }

        const bool pf = (kt + 1 < NK);
        const uint32_t sb = (uint32_t)((st ^ 1) * STG_BYTES);
        const int ko = (kt + 1) * BK;
        const uint32_t stage = sm_base + (uint32_t)(st * STG_BYTES);

        // ---- k16 = 0..2: full compute + interleaved producer issue ----
#pragma unroll
        for (int k16 = 0; k16 < 3; k16++) {
            const uint32_t kb = (uint32_t)(k16 * 16 * 2);

            uint32_t A[2][4];
#pragma unroll
            for (int mi = 0; mi < 2; mi++)
                LDSM_X4(A[mi], stage + A_OFF(mi) + kb);

            uint32_t B[NSEG][4];
#pragma unroll
            for (int s = 0; s < NSEG; s++)
                LDSM_X4(B[s], stage + B_OFF(s) + kb);

            if (k16 == 0 && pf) {
#pragma unroll
                for (int j = 0; j < 4; j++)
                    cp_async16(sa_x + sb + (uint32_t)(16 * j * SROW) * 2,
                               gx0 + (size_t)(16 * j) * DIN + ko);
            } else if (k16 == 1 && pf) {
#pragma unroll
                for (int jw = 0; jw < 4; jw++) {
                    const size_t goff =
                        ((size_t)(jw >> 1) * DSTATE + 16 * (jw & 1)) * DIN;
                    cp_async16(sa_w + sb + (uint32_t)(16 * jw * SROW) * 2,
                               gw0 + goff + ko);
                }
            } else if (k16 == 2) {
                if (pf) {
#pragma unroll
                    for (int jw = 4; jw < 8; jw++) {
                        const size_t goff =
                            ((size_t)(jw >> 1) * DSTATE + 16 * (jw & 1)) * DIN;
                        cp_async16(sa_w + sb + (uint32_t)(16 * jw * SROW) * 2,
                                   gw0 + goff + ko);
                    }
                }
                CP_COMMIT();  // uniform one group per kt (may be empty at tail)
            }

#pragma unroll
            for (int s = 0; s < NSEG; s++) {
#pragma unroll
                for (int ni = 0; ni < 2; ni++) {
#pragma unroll
                    for (int mi = 0; mi < 2; mi++) {
                        MMA_F16(acc[s][mi][ni], A[mi], B[s][ni * 2],
                                B[s][ni * 2 + 1]);
                    }
                }
            }
        }

        // ---- k16 = 3: load all fragments; MMA segs 0,1 now; hold segs 2,3 ----
        {
            const uint32_t kb = (uint32_t)(3 * 16 * 2);
#pragma unroll
            for (int mi = 0; mi < 2; mi++)
                LDSM_X4(Ah[mi], stage + A_OFF(mi) + kb);

            uint32_t B01[2][4];
#pragma unroll
            for (int s = 0; s < 2; s++)
                LDSM_X4(B01[s], stage + B_OFF(s) + kb);
#pragma unroll
            for (int sh = 0; sh < 2; sh++)
                LDSM_X4(Bh[sh], stage + B_OFF(2 + sh) + kb);

#pragma unroll
            for (int s = 0; s < 2; s++) {
#pragma unroll
                for (int ni = 0; ni < 2; ni++) {
#pragma unroll
                    for (int mi = 0; mi < 2; mi++) {
                        MMA_F16(acc[s][mi][ni], Ah[mi], B01[s][ni * 2],
                                B01[s][ni * 2 + 1]);
                    }
                }
            }
        }

        st ^= 1;
    }

    // ---- drain: deferred MMAs of the final k16=3, segs 2,3 ----
#pragma unroll
    for (int sh = 0; sh < 2; sh++) {
#pragma unroll
        for (int ni = 0; ni < 2; ni++) {
#pragma unroll
            for (int mi = 0; mi < 2; mi++) {
                MMA_F16(acc[2 + sh][mi][ni], Ah[mi], Bh[sh][ni * 2],
                        Bh[sh][ni * 2 + 1]);
            }
        }
    }

    // ---- epilogue: bias, plateau, gate, sum + 0.1 * signed geo-mean ----
    const int bbase = bm * BM;
    const int dbase = bn * BN;

#pragma unroll
    for (int mi = 0; mi < 2; mi++) {
#pragma unroll
        for (int hh = 0; hh < 2; hh++) {
            const int rloc = wm * 32 + mi * 16 + g + hh * 8;
            const int brow = bbase + rloc;
            float4 gv = *(const float4*)(&g_gates[brow * 4]);
            float gt[NSEG] = {gv.x, gv.y, gv.z, gv.w};
#pragma unroll
            for (int ni = 0; ni < 2; ni++) {
#pragma unroll
                for (int e = 0; e < 2; e++) {
                    const int d = dbase + wn * 16 + ni * 8 + qb * 2 + e;
                    float sumv = 0.f, prodv = 1.f;
#pragma unroll
                    for (int s = 0; s < NSEG; s++) {
                        float seg = acc[s][mi][ni][hh * 2 + e] + b_seg[s * DSTATE + d];
                        float z = 5.f * (seg - th[s * DSTATE + d]);
                        float p = 1.f / (1.f + __expf(-z));
                        float vv = seg * p * gt[s];
                        sumv += vv;
                        prodv *= vv;
                    }
                    float r4 = sqrtf(sqrtf(fabsf(prodv)));
                    out[(size_t)brow * DSTATE + d] = sumv + 0.1f * copysignf(r4, prodv);
                }
            }
        }
    }
}

// ---------------------------------------------------------------------------
extern "C" void kernel_launch(void* const* d_in, const int* in_sizes, int n_in,
                              void* d_out, int out_size) {
    const float* x      = (const float*)d_in[0];
    const float* W_seg  = (const float*)d_in[1];
    const float* b_seg  = (const float*)d_in[2];
    const float* thresh = (const float*)d_in[3];
    const float* W_gate = (const float*)d_in[4];
    const float* b_gate = (const float*)d_in[5];
    float* out = (float*)d_out;
    (void)in_sizes; (void)n_in; (void)out_size;

    __half* gx;
    __half* gw;
    cudaGetSymbolAddress((void**)&gx, g_xh);
    cudaGetSymbolAddress((void**)&gw, g_wh);

    cudaFuncSetAttribute(dendritic_kernel,
                         cudaFuncAttributeMaxDynamicSharedMemorySize, SMEM_BYTES);

    tohalf_kernel<<<1184, 256>>>(x, gx, BROWS * DIN / 4);
    tohalf_kernel<<<1184, 256>>>(W_seg, gw, NSEG * DSTATE * DIN / 4);
    gate_kernel<<<BROWS / 8, 256>>>(x, W_gate, b_gate);

    dim3 grid(BROWS / BM, DSTATE / BN);  // (128, 64), bm fast
    dendritic_kernel<<<grid, 128, SMEM_BYTES>>>(b_seg, thresh, out);
}